// round 8
// baseline (speedup 1.0000x reference)
#include <cuda_runtime.h>
#include <cuda_fp16.h>
#include <cstdint>

#define NN 100000
#define EE 3200000
#define DD 128
#define EPS 1e-5f

#define RBM 64                               // rows per GEMM block
#define GEMM_BLOCKS ((NN + RBM - 1) / RBM)   // 1563

// smem layout for tf32 GEMM
#define SA_STRIDE 260                        // 256 + 4 pad
#define SB_STRIDE 136                        // 128 + 8 pad
#define SA_FLOATS (64 * SA_STRIDE)           // 16640
#define SB_FLOATS (256 * SB_STRIDE)          // 34816
#define GEMM_SMEM ((SA_FLOATS + SB_FLOATS) * 4)   // 205824 B

// Scratch (allocation-free rule: __device__ globals)
__device__ __half g_hhalf[NN * DD];  // fp16 copy of h for the gather
__device__ float g_neigh[NN * DD];   // mean-aggregated neighbor features
__device__ float g_rst[NN * DD];     // post-relu activations
__device__ int   g_cnt[NN];          // degree histogram
__device__ int   g_off[NN];          // CSR exclusive offsets
__device__ int   g_cursor[NN];       // fill cursors
__device__ int   g_sorted[EE];       // src sorted by dst
__device__ float g_colsum[DD];
__device__ float g_colsumsq[DD];
__device__ float g_coefA[DD];
__device__ float g_coefB[DD];

// ---------------------------------------------------------------------------
// K0: zero counters + stats
// ---------------------------------------------------------------------------
__global__ void zero_kernel() {
    int i = blockIdx.x * blockDim.x + threadIdx.x;
    int stride = gridDim.x * blockDim.x;
    for (int f = i; f < NN; f += stride) g_cnt[f] = 0;
    if (i < DD) { g_colsum[i] = 0.f; g_colsumsq[i] = 0.f; }
}

// ---------------------------------------------------------------------------
// K1: fused degree histogram + fp16 conversion of h.
// The hist atomics are latency-bound (issue ~1.6%); the streaming conversion
// rides in the idle issue/LSU slots for ~free.
// ---------------------------------------------------------------------------
__global__ void hist_convert_kernel(const int* __restrict__ dst,
                                    const float* __restrict__ h) {
    int i = blockIdx.x * blockDim.x + threadIdx.x;
    int stride = gridDim.x * blockDim.x;

    // fp16 conversion: float4 -> 4 halves (uint2)
    const float4* h4 = (const float4*)h;
    uint2* o = (uint2*)g_hhalf;
    const int nf4 = NN * DD / 4;
    for (int f = i; f < nf4; f += stride) {
        float4 v = h4[f];
        __half2 lo = __floats2half2_rn(v.x, v.y);
        __half2 hi = __floats2half2_rn(v.z, v.w);
        uint2 u;
        u.x = *(uint32_t*)&lo;
        u.y = *(uint32_t*)&hi;
        o[f] = u;
    }

    // histogram (int4 edge loads)
    const int4* d4 = (const int4*)dst;
    const int n4 = EE / 4;
    for (int e = i; e < n4; e += stride) {
        int4 d = __ldg(&d4[e]);
        atomicAdd(&g_cnt[d.x], 1);
        atomicAdd(&g_cnt[d.y], 1);
        atomicAdd(&g_cnt[d.z], 1);
        atomicAdd(&g_cnt[d.w], 1);
    }
}

// ---------------------------------------------------------------------------
// K2: single-block exclusive scan of g_cnt -> g_off / g_cursor
// ---------------------------------------------------------------------------
#define SCAN_T 1024
#define CHUNK  ((NN + SCAN_T - 1) / SCAN_T)   // 98
__global__ void __launch_bounds__(SCAN_T, 1)
scan_kernel() {
    __shared__ int ss[SCAN_T];
    int t = threadIdx.x;
    int beg = t * CHUNK;
    int end = min(beg + CHUNK, NN);
    int s = 0;
    for (int i = beg; i < end; i++) s += g_cnt[i];
    ss[t] = s;
    __syncthreads();
    for (int d = 1; d < SCAN_T; d <<= 1) {
        int v = (t >= d) ? ss[t - d] : 0;
        __syncthreads();
        ss[t] += v;
        __syncthreads();
    }
    int run = ss[t] - s;
    for (int i = beg; i < end; i++) {
        g_off[i] = run;
        g_cursor[i] = run;
        run += g_cnt[i];
    }
}

// ---------------------------------------------------------------------------
// K3: CSR fill — counting sort of src by dst (int4 loads)
// ---------------------------------------------------------------------------
__global__ void fill_kernel(const int* __restrict__ src,
                            const int* __restrict__ dst) {
    int i = blockIdx.x * blockDim.x + threadIdx.x;
    int stride = gridDim.x * blockDim.x;
    const int4* s4 = (const int4*)src;
    const int4* d4 = (const int4*)dst;
    const int n4 = EE / 4;
    for (int e = i; e < n4; e += stride) {
        int4 d = __ldg(&d4[e]);
        int4 s = __ldg(&s4[e]);
        g_sorted[atomicAdd(&g_cursor[d.x], 1)] = s.x;
        g_sorted[atomicAdd(&g_cursor[d.y], 1)] = s.y;
        g_sorted[atomicAdd(&g_cursor[d.z], 1)] = s.z;
        g_sorted[atomicAdd(&g_cursor[d.w], 1)] = s.w;
    }
}

// ---------------------------------------------------------------------------
// K4: aggregation over fp16 h — warp per node, lane = 4 halves (uint2),
// unroll 8 rows; fp32 accumulation; half the gather traffic of fp32.
// ---------------------------------------------------------------------------
__device__ __forceinline__ void h2acc(float4& a, uint2 u) {
    __half2 lo = *(__half2*)&u.x;
    __half2 hi = *(__half2*)&u.y;
    float2 f0 = __half22float2(lo);
    float2 f1 = __half22float2(hi);
    a.x += f0.x; a.y += f0.y; a.z += f1.x; a.w += f1.y;
}

__global__ void __launch_bounds__(256)
agg_kernel() {
    int lane = threadIdx.x & 31;
    int gw = blockIdx.x * 8 + (threadIdx.x >> 5);
    int nw = gridDim.x * 8;
    const uint2* h2 = (const uint2*)g_hhalf;   // 32 uint2 per row
    for (int row = gw; row < NN; row += nw) {
        int beg = __ldg(&g_off[row]);
        int deg = __ldg(&g_cnt[row]);
        float4 a0 = make_float4(0.f, 0.f, 0.f, 0.f);
        float4 a1 = a0, a2 = a0, a3 = a0;
        int j = 0;
        for (; j + 8 <= deg; j += 8) {
            int s0 = __ldg(&g_sorted[beg + j]);
            int s1 = __ldg(&g_sorted[beg + j + 1]);
            int s2 = __ldg(&g_sorted[beg + j + 2]);
            int s3 = __ldg(&g_sorted[beg + j + 3]);
            int s4 = __ldg(&g_sorted[beg + j + 4]);
            int s5 = __ldg(&g_sorted[beg + j + 5]);
            int s6 = __ldg(&g_sorted[beg + j + 6]);
            int s7 = __ldg(&g_sorted[beg + j + 7]);
            uint2 v0 = __ldg(&h2[(size_t)s0 * 32 + lane]);
            uint2 v1 = __ldg(&h2[(size_t)s1 * 32 + lane]);
            uint2 v2 = __ldg(&h2[(size_t)s2 * 32 + lane]);
            uint2 v3 = __ldg(&h2[(size_t)s3 * 32 + lane]);
            uint2 v4 = __ldg(&h2[(size_t)s4 * 32 + lane]);
            uint2 v5 = __ldg(&h2[(size_t)s5 * 32 + lane]);
            uint2 v6 = __ldg(&h2[(size_t)s6 * 32 + lane]);
            uint2 v7 = __ldg(&h2[(size_t)s7 * 32 + lane]);
            h2acc(a0, v0); h2acc(a1, v1); h2acc(a2, v2); h2acc(a3, v3);
            h2acc(a0, v4); h2acc(a1, v5); h2acc(a2, v6); h2acc(a3, v7);
        }
        for (; j < deg; j++) {
            int s = __ldg(&g_sorted[beg + j]);
            h2acc(a0, __ldg(&h2[(size_t)s * 32 + lane]));
        }
        float inv = 1.0f / fmaxf((float)deg, 1.0f);
        float4 r;
        r.x = (a0.x + a1.x + a2.x + a3.x) * inv;
        r.y = (a0.y + a1.y + a2.y + a3.y) * inv;
        r.z = (a0.z + a1.z + a2.z + a3.z) * inv;
        r.w = (a0.w + a1.w + a2.w + a3.w) * inv;
        ((float4*)(g_neigh + (size_t)row * DD))[lane] = r;
    }
}

// ---------------------------------------------------------------------------
// K5: TF32 tensor-core dual GEMM (concat K=256):
//   rst = relu([h | neigh] @ [Ws; Wn] + b), fused BN column stats.
// ---------------------------------------------------------------------------
__device__ __forceinline__ uint32_t f2tf32(float v) {
    uint32_t x;
    asm("cvt.rna.tf32.f32 %0, %1;" : "=r"(x) : "f"(v));
    return x;
}

__global__ void __launch_bounds__(256, 1)
dual_gemm_tf32(const float* __restrict__ h,
               const float* __restrict__ Wself,
               const float* __restrict__ Wneigh,
               const float* __restrict__ bias) {
    extern __shared__ float sm[];
    float* sA = sm;              // 64 x SA_STRIDE
    float* sB = sm + SA_FLOATS;  // 256 x SB_STRIDE

    const int t    = threadIdx.x;
    const int lane = t & 31;
    const int wid  = t >> 5;
    const int gid  = lane >> 2;   // 0..7
    const int tig  = lane & 3;    // 0..3
    const int wm   = wid & 1;     // warp row 0..1
    const int wn   = wid >> 1;    // warp col 0..3
    const int row_base = blockIdx.x * RBM;

    // --- cooperative A load: 64 rows x 256 cols = [h | neigh], cvt tf32 ---
    for (int f = t; f < 64 * 64; f += 256) {       // 64 float4 per row
        int r  = f >> 6;
        int c4 = f & 63;
        int row = row_base + r;
        float4 v = make_float4(0.f, 0.f, 0.f, 0.f);
        if (row < NN) {
            if (c4 < 32) v = ((const float4*)(h + (size_t)row * DD))[c4];
            else         v = ((const float4*)(g_neigh + (size_t)row * DD))[c4 - 32];
        }
        float* p = &sA[r * SA_STRIDE + c4 * 4];
        p[0] = __uint_as_float(f2tf32(v.x));
        p[1] = __uint_as_float(f2tf32(v.y));
        p[2] = __uint_as_float(f2tf32(v.z));
        p[3] = __uint_as_float(f2tf32(v.w));
    }
    // --- cooperative B load: rows 0..127 = Ws, 128..255 = Wn ---
    for (int f = t; f < 256 * 32; f += 256) {      // 32 float4 per row
        int k  = f >> 5;
        int n4 = f & 31;
        const float4* W = (k < 128) ? (const float4*)Wself : (const float4*)Wneigh;
        float4 v = __ldg(&W[(k & 127) * 32 + n4]);
        float* p = &sB[k * SB_STRIDE + n4 * 4];
        p[0] = __uint_as_float(f2tf32(v.x));
        p[1] = __uint_as_float(f2tf32(v.y));
        p[2] = __uint_as_float(f2tf32(v.z));
        p[3] = __uint_as_float(f2tf32(v.w));
    }
    __syncthreads();

    float acc[2][4][4];
    #pragma unroll
    for (int mi = 0; mi < 2; mi++)
        #pragma unroll
        for (int ni = 0; ni < 4; ni++)
            #pragma unroll
            for (int c = 0; c < 4; c++) acc[mi][ni][c] = 0.f;

    for (int k = 0; k < 256; k += 8) {
        uint32_t a[2][4], b[4][2];
        #pragma unroll
        for (int mi = 0; mi < 2; mi++) {
            int r0 = wm * 32 + mi * 16 + gid;
            a[mi][0] = __float_as_uint(sA[r0 * SA_STRIDE + k + tig]);
            a[mi][1] = __float_as_uint(sA[(r0 + 8) * SA_STRIDE + k + tig]);
            a[mi][2] = __float_as_uint(sA[r0 * SA_STRIDE + k + tig + 4]);
            a[mi][3] = __float_as_uint(sA[(r0 + 8) * SA_STRIDE + k + tig + 4]);
        }
        #pragma unroll
        for (int ni = 0; ni < 4; ni++) {
            int n0 = wn * 32 + ni * 8 + gid;
            b[ni][0] = __float_as_uint(sB[(k + tig) * SB_STRIDE + n0]);
            b[ni][1] = __float_as_uint(sB[(k + tig + 4) * SB_STRIDE + n0]);
        }
        #pragma unroll
        for (int mi = 0; mi < 2; mi++)
            #pragma unroll
            for (int ni = 0; ni < 4; ni++) {
                asm volatile(
                    "mma.sync.aligned.m16n8k8.row.col.f32.tf32.tf32.f32 "
                    "{%0,%1,%2,%3}, {%4,%5,%6,%7}, {%8,%9}, {%0,%1,%2,%3};"
                    : "+f"(acc[mi][ni][0]), "+f"(acc[mi][ni][1]),
                      "+f"(acc[mi][ni][2]), "+f"(acc[mi][ni][3])
                    : "r"(a[mi][0]), "r"(a[mi][1]), "r"(a[mi][2]), "r"(a[mi][3]),
                      "r"(b[ni][0]), "r"(b[ni][1]));
            }
    }

    // --- epilogue: bias, relu, store, per-thread BN stats ---
    float2 bv[4];
    #pragma unroll
    for (int ni = 0; ni < 4; ni++) {
        int col = wn * 32 + ni * 8 + 2 * tig;
        bv[ni] = *(const float2*)&bias[col];
    }

    float lsum[4][2], lsq[4][2];
    #pragma unroll
    for (int ni = 0; ni < 4; ni++) {
        lsum[ni][0] = lsum[ni][1] = 0.f;
        lsq[ni][0] = lsq[ni][1] = 0.f;
    }

    #pragma unroll
    for (int mi = 0; mi < 2; mi++) {
        #pragma unroll
        for (int half = 0; half < 2; half++) {
            int row = row_base + wm * 32 + mi * 16 + half * 8 + gid;
            if (row < NN) {
                #pragma unroll
                for (int ni = 0; ni < 4; ni++) {
                    int col = wn * 32 + ni * 8 + 2 * tig;
                    float v0 = fmaxf(acc[mi][ni][half * 2]     + bv[ni].x, 0.f);
                    float v1 = fmaxf(acc[mi][ni][half * 2 + 1] + bv[ni].y, 0.f);
                    lsum[ni][0] += v0; lsq[ni][0] += v0 * v0;
                    lsum[ni][1] += v1; lsq[ni][1] += v1 * v1;
                    *(float2*)&g_rst[(size_t)row * DD + col] = make_float2(v0, v1);
                }
            }
        }
    }

    // warp-reduce stats over gid lanes, then global atomics
    #pragma unroll
    for (int ni = 0; ni < 4; ni++)
        #pragma unroll
        for (int s = 0; s < 2; s++) {
            #pragma unroll
            for (int off = 4; off <= 16; off <<= 1) {
                lsum[ni][s] += __shfl_xor_sync(0xffffffffu, lsum[ni][s], off);
                lsq[ni][s]  += __shfl_xor_sync(0xffffffffu, lsq[ni][s],  off);
            }
        }
    if (gid == 0) {
        #pragma unroll
        for (int ni = 0; ni < 4; ni++) {
            int col = wn * 32 + ni * 8 + 2 * tig;
            atomicAdd(&g_colsum[col],       lsum[ni][0]);
            atomicAdd(&g_colsum[col + 1],   lsum[ni][1]);
            atomicAdd(&g_colsumsq[col],     lsq[ni][0]);
            atomicAdd(&g_colsumsq[col + 1], lsq[ni][1]);
        }
    }
}

// ---------------------------------------------------------------------------
// K6: finalize BN coefficients
// ---------------------------------------------------------------------------
__global__ void finalize_kernel(const float* __restrict__ gamma,
                                const float* __restrict__ beta) {
    int c = threadIdx.x;
    const float invN = 1.0f / (float)NN;
    float mean = g_colsum[c] * invN;
    float var  = g_colsumsq[c] * invN - mean * mean;
    float a = gamma[c] * rsqrtf(var + EPS);
    g_coefA[c] = a;
    g_coefB[c] = beta[c] - mean * a;
}

// ---------------------------------------------------------------------------
// K7: out = h + rst * A[c] + B[c]
// ---------------------------------------------------------------------------
__global__ void output_kernel(const float* __restrict__ h,
                              float* __restrict__ out) {
    int i = blockIdx.x * blockDim.x + threadIdx.x;
    int stride = gridDim.x * blockDim.x;
    const int nf4 = NN * DD / 4;
    for (int f = i; f < nf4; f += stride) {
        int cg = f & 31;
        float4 a  = ((const float4*)g_coefA)[cg];
        float4 bb = ((const float4*)g_coefB)[cg];
        float4 hv = ((const float4*)h)[f];
        float4 rv = ((const float4*)g_rst)[f];
        float4 o;
        o.x = hv.x + rv.x * a.x + bb.x;
        o.y = hv.y + rv.y * a.y + bb.y;
        o.z = hv.z + rv.z * a.z + bb.z;
        o.w = hv.w + rv.w * a.w + bb.w;
        ((float4*)out)[f] = o;
    }
}

// ---------------------------------------------------------------------------
extern "C" void kernel_launch(void* const* d_in, const int* in_sizes, int n_in,
                              void* d_out, int out_size) {
    const float* h      = (const float*)d_in[0];
    const int*   src    = (const int*)d_in[1];
    const int*   dst    = (const int*)d_in[2];
    const float* Wself  = (const float*)d_in[3];
    const float* Wneigh = (const float*)d_in[4];
    const float* bias   = (const float*)d_in[5];
    const float* gamma  = (const float*)d_in[6];
    const float* beta   = (const float*)d_in[7];
    float*       out    = (float*)d_out;

    zero_kernel<<<256, 256>>>();
    hist_convert_kernel<<<2048, 256>>>(dst, h);
    scan_kernel<<<1, SCAN_T>>>();
    fill_kernel<<<2048, 256>>>(src, dst);
    agg_kernel<<<2048, 256>>>();

    cudaFuncSetAttribute(dual_gemm_tf32,
                         cudaFuncAttributeMaxDynamicSharedMemorySize,
                         GEMM_SMEM);
    dual_gemm_tf32<<<GEMM_BLOCKS, 256, GEMM_SMEM>>>(h, Wself, Wneigh, bias);

    finalize_kernel<<<1, DD>>>(gamma, beta);
    output_kernel<<<2048, 256>>>(h, out);
}